// round 8
// baseline (speedup 1.0000x reference)
#include <cuda_runtime.h>
#include <cstdint>

// AggrSum: out[v, :] = sum over rows n with X_node[n] == v of H[n, :]
// H: [N, 64] f32 (sequential, read-once -> streaming loads),
// X_node: [N] int32, out: [100000, 64] f32 (L2-resident RED target).
//
// Scatter with red.global.add.v4.f32. Architecture is atomic-ALU-bound at the
// L2 slices (~32M 16B RED ops); this version maximizes read/RED overlap:
// 4 rows per 16-thread group, one broadcast int4 idx load, 4 independent
// streaming LDG.128s in flight per thread.

constexpr int D  = 64;
constexpr int D4 = D / 4;   // 16 float4 chunks per row

__global__ void zero_out_kernel(float4* __restrict__ out, int n4) {
    int i = blockIdx.x * blockDim.x + threadIdx.x;
    if (i < n4) out[i] = make_float4(0.f, 0.f, 0.f, 0.f);
}

__global__ __launch_bounds__(256)
void scatter_add_kernel(const float4* __restrict__ H4,
                        const int4* __restrict__ idx4,
                        float* __restrict__ out,
                        int Nquad) {
    int t = blockIdx.x * blockDim.x + threadIdx.x;
    int quad = t >> 4;      // each 16-thread group handles rows 4q .. 4q+3
    int c    = t & 15;      // float4 chunk within a row
    if (quad >= Nquad) return;

    // One broadcast 16B load serves all 4 row ids for the whole group.
    int4 v = __ldg(idx4 + quad);

    const float4* hrow = H4 + (size_t)quad * (4 * D4) + c;
    // 4 independent streaming loads: 64B in flight per thread, 2KB per warp.
    float4 h0 = __ldcs(hrow + 0 * D4);
    float4 h1 = __ldcs(hrow + 1 * D4);
    float4 h2 = __ldcs(hrow + 2 * D4);
    float4 h3 = __ldcs(hrow + 3 * D4);

    float* p0 = out + (size_t)v.x * D + (size_t)c * 4;
    float* p1 = out + (size_t)v.y * D + (size_t)c * 4;
    float* p2 = out + (size_t)v.z * D + (size_t)c * 4;
    float* p3 = out + (size_t)v.w * D + (size_t)c * 4;

    asm volatile("red.global.add.v4.f32 [%0], {%1, %2, %3, %4};"
                 :: "l"(p0), "f"(h0.x), "f"(h0.y), "f"(h0.z), "f"(h0.w) : "memory");
    asm volatile("red.global.add.v4.f32 [%0], {%1, %2, %3, %4};"
                 :: "l"(p1), "f"(h1.x), "f"(h1.y), "f"(h1.z), "f"(h1.w) : "memory");
    asm volatile("red.global.add.v4.f32 [%0], {%1, %2, %3, %4};"
                 :: "l"(p2), "f"(h2.x), "f"(h2.y), "f"(h2.z), "f"(h2.w) : "memory");
    asm volatile("red.global.add.v4.f32 [%0], {%1, %2, %3, %4};"
                 :: "l"(p3), "f"(h3.x), "f"(h3.y), "f"(h3.z), "f"(h3.w) : "memory");
}

extern "C" void kernel_launch(void* const* d_in, const int* in_sizes, int n_in,
                              void* d_out, int out_size) {
    const float4* H4   = (const float4*)d_in[0];   // H [N, 64] as [N, 16] float4
    const int4*   idx4 = (const int4*)d_in[1];     // X_node int32 [N] as int4
    float*        out  = (float*)d_out;            // [V, 64] f32

    int N  = in_sizes[1];         // 2,000,000 (divisible by 4)
    int n4 = out_size / 4;

    // 1) Zero the poisoned output (dirty lines land in L2 -> REDs hit L2).
    zero_out_kernel<<<(n4 + 255) / 256, 256>>>((float4*)out, n4);

    // 2) Scatter-add: sequential H stream, L2-side vector reductions.
    int Nquad = N / 4;
    long long threads_total = (long long)Nquad * 16;
    int blocks = (int)((threads_total + 255) / 256);
    scatter_add_kernel<<<blocks, 256>>>(H4, idx4, out, Nquad);
}